// round 5
// baseline (speedup 1.0000x reference)
#include <cuda_runtime.h>

#define K_CODES 16384
#define NSAMP   4096
#define DIM     14
#define HW      1024
#define Q_ELEMS 57344            // 4 * 14 * 1024
#define WPB     8                // warps (= samples) per block
#define NBLK    (NSAMP / WPB)    // 512 blocks, all resident -> spin barrier safe
#define HPB     (K_CODES / NBLK) // 32 histogram entries per block

// Module-load zero-initialized; every call restores zeros behind itself so
// each execution (eager correctness run or graph replay) starts identically.
__device__ float g_avg[K_CODES];
__device__ float g_ent_sum;
__device__ float g_hist_sum;
__device__ int   g_done;    // phase-1 arrival
__device__ int   g_done2;   // finalize arrival (certifies spin exit)

__device__ __forceinline__ float warp_sum(float v) {
#pragma unroll
    for (int off = 16; off > 0; off >>= 1)
        v += __shfl_xor_sync(0xffffffffu, v, off);
    return v;
}

// ---------------------------------------------------------------------------
// Single persistent kernel.
// Phase 1 (warp per sample): lane j<14 owns dim j. Ballot -> big-endian index;
//   shuffle reductions -> norm and the EXACT closed-form entropy (the softmax
//   over +-1 codes factorizes into per-dim Bernoullis):
//     a_j = 400|xn_j|, logS = sum log1p(e^-a_j), H = logS + sum a_j*sig(-a_j)
//   Survivor scatter into g_avg: lane = subset mask of dims with a_j < 30
//   (dropped probs < e^-30, below fp32 noise in the reference itself).
// Grid barrier (all NBLK blocks resident by construction).
// Phase 2: each block folds its 32 histogram entries into sum a*log(a+eps),
//   zeroing them behind itself; last block emits el and resets the scalars.
// ---------------------------------------------------------------------------
__global__ __launch_bounds__(32 * WPB) void lfq_fused(const float* __restrict__ x,
                                                      float* __restrict__ out) {
    __shared__ float sc[WPB][DIM];
    __shared__ int   st[WPB][DIM];
    __shared__ float wents[WPB];
    __shared__ float wsum2[WPB];

    const int tid  = threadIdx.x;
    const int wid  = tid >> 5;
    const int lane = tid & 31;
    const int s    = blockIdx.x * WPB + wid;    // sample id
    const int b    = s >> 10;
    const int n    = s & (HW - 1);

    // ---- phase 1: load, sign, index ----
    float v = 0.0f;
    if (lane < DIM) {
        v = x[(b * DIM + lane) * HW + n];
        out[(b * DIM + lane) * HW + n] = (v > 0.0f) ? 1.0f : -1.0f;
    }

    const float inv = rsqrtf(warp_sum(v * v));

    const unsigned bal = __ballot_sync(0xffffffffu, v > 0.0f) & 0x3FFFu;
    const int idx = (int)(__brev(bal) >> 18);    // big-endian bit order
    if (lane == 0) out[Q_ELEMS + 1 + s] = (float)idx;

    // closed-form softmax stats
    const float a = (lane < DIM) ? 400.0f * fabsf(v) * inv : 1e30f;
    const float e = __expf(-a);                  // exactly 0 for pad lanes
    const float logS = warp_sum(log1pf(e));
    const float ent  = logS + warp_sum(a * e / (1.0f + e));
    if (lane == 0) wents[wid] = ent;

    // rank the "small" (flippable) dims into shared
    const bool small = (lane < DIM) && (a < 30.0f);
    const unsigned bm = __ballot_sync(0xffffffffu, small);
    const int m = __popc(bm);
    if (small) {
        const int rank = __popc(bm & ((1u << lane) - 1u));
        sc[wid][rank] = a;
        st[wid][rank] = 1 << (13 - lane);
    }
    __syncwarp();

    // survivor scatter: lane = subset mask (one pass for ~95% of samples)
    const float invS = __expf(-logS);
    const int nm = 1 << m;
    for (int mask = lane; mask < nm; mask += 32) {
        float c = 0.0f;
        int tog = 0;
        for (int j = 0; j < m; j++)
            if ((mask >> j) & 1) { c += sc[wid][j]; tog ^= st[wid][j]; }
        if (c < 30.0f)
            atomicAdd(&g_avg[idx ^ tog], __expf(-c) * invS);
    }

    // block entropy partial -> one atomic per block
    __syncthreads();
    if (tid < WPB) {
        float t = wents[tid];
#pragma unroll
        for (int off = WPB / 2; off > 0; off >>= 1)
            t += __shfl_xor_sync((1u << WPB) - 1u, t, off);
        if (tid == 0) atomicAdd(&g_ent_sum, t);
    }

    // ---- grid barrier: all blocks resident, spin is safe ----
    __threadfence();                 // make scatter visible before arrival
    __syncthreads();
    if (tid == 0) {
        atomicAdd(&g_done, 1);
        while (atomicAdd(&g_done, 0) < NBLK) { }
    }
    __syncthreads();
    __threadfence();                 // acquire other blocks' g_avg writes

    // ---- phase 2: histogram fold (32 entries per block) ----
    float ms = 0.0f;
    if (tid < HPB) {
        const int i = blockIdx.x * HPB + tid;
        const float av = g_avg[i] * (1.0f / (float)NSAMP);
        g_avg[i] = 0.0f;             // restore zeros for next replay
        ms = av * logf(av + 1e-9f);
    }
    if (tid < 32) {
        ms = warp_sum(ms);
        if (tid == 0) {
            atomicAdd(&g_hist_sum, ms);
            __threadfence();
            const int d = atomicAdd(&g_done2, 1);
            if (d == NBLK - 1) {
                // every block has passed the spin (it arrived here), so
                // resetting g_done is safe now.
                const float hs = atomicAdd(&g_hist_sum, 0.0f);
                const float es = atomicAdd(&g_ent_sum, 0.0f);
                // el = entro_mean - mean_entro = es/N + sum a*log(a+eps)
                out[Q_ELEMS] = es * (1.0f / (float)NSAMP) + hs;
                g_hist_sum = 0.0f;
                g_ent_sum  = 0.0f;
                g_done     = 0;
                g_done2    = 0;
            }
        }
    }
}

extern "C" void kernel_launch(void* const* d_in, const int* in_sizes, int n_in,
                              void* d_out, int out_size) {
    const float* x = (const float*)d_in[0];
    float* out = (float*)d_out;
    lfq_fused<<<NBLK, 32 * WPB>>>(x, out);
}

// round 6
// speedup vs baseline: 1.0019x; 1.0019x over previous
#include <cuda_runtime.h>

#define K_CODES 16384
#define NSAMP   4096
#define DIM     14
#define HW      1024
#define Q_ELEMS 57344            // 4 * 14 * 1024
#define WPB     8                // warps (= samples) per block
#define NBLK    (NSAMP / WPB)    // 512 blocks, all resident -> spin barrier safe
#define HPB     (K_CODES / NBLK) // 32 histogram entries per block

// Module-load zero-initialized; every call restores zeros behind itself so
// each execution (eager correctness run or graph replay) starts identically.
__device__ float g_avg[K_CODES];
__device__ float g_ent_sum;
__device__ float g_hist_sum;
__device__ volatile int g_done;  // phase-1 arrival (spin target: plain loads)
__device__ int   g_done2;        // finalize arrival (certifies spin exit)

__device__ __forceinline__ float warp_sum(float v) {
#pragma unroll
    for (int off = 16; off > 0; off >>= 1)
        v += __shfl_xor_sync(0xffffffffu, v, off);
    return v;
}

// ---------------------------------------------------------------------------
// Single persistent kernel.
// Phase 1 (warp per sample): lane j<14 owns dim j. Ballot -> big-endian index;
//   shuffle reductions -> norm and the EXACT closed-form entropy (softmax over
//   +-1 codes factorizes into per-dim Bernoullis):
//     a_j = 400|xn_j|, logS = sum log(1+e^-a_j), H = logS + sum a_j*sig(-a_j)
//   Survivor scatter into g_avg: lane = subset mask of dims with a_j < 30
//   (dropped probs < e^-30, below fp32 noise in the reference itself).
// Grid barrier: release = fence + one atomicAdd/block; wait = volatile LOAD
//   spin (no RMW contention) + nanosleep backoff; acquire = fence after exit.
// Phase 2: each block folds its 32 histogram entries into sum a*log(a+eps),
//   zeroing them behind itself; last block emits el and resets the scalars.
// ---------------------------------------------------------------------------
__global__ __launch_bounds__(32 * WPB) void lfq_fused(const float* __restrict__ x,
                                                      float* __restrict__ out) {
    __shared__ float sc[WPB][DIM];
    __shared__ int   st[WPB][DIM];
    __shared__ float wents[WPB];

    const int tid  = threadIdx.x;
    const int wid  = tid >> 5;
    const int lane = tid & 31;
    const int s    = blockIdx.x * WPB + wid;    // sample id
    const int b    = s >> 10;
    const int n    = s & (HW - 1);

    // ---- phase 1: load, sign, index ----
    float v = 0.0f;
    if (lane < DIM) {
        v = x[(b * DIM + lane) * HW + n];
        out[(b * DIM + lane) * HW + n] = (v > 0.0f) ? 1.0f : -1.0f;
    }

    const float inv = rsqrtf(warp_sum(v * v));

    const unsigned bal = __ballot_sync(0xffffffffu, v > 0.0f) & 0x3FFFu;
    const int idx = (int)(__brev(bal) >> 18);    // big-endian bit order
    if (lane == 0) out[Q_ELEMS + 1 + s] = (float)idx;

    // closed-form softmax stats (fast-math log: 2^-21 rel err vs 1e-3 budget)
    const float a = (lane < DIM) ? 400.0f * fabsf(v) * inv : 1e30f;
    const float e = __expf(-a);                  // exactly 0 for pad lanes
    const float logS = warp_sum(__logf(1.0f + e));
    const float ent  = logS + warp_sum(a * e / (1.0f + e));
    if (lane == 0) wents[wid] = ent;

    // rank the "small" (flippable) dims into shared
    const bool small = (lane < DIM) && (a < 30.0f);
    const unsigned bm = __ballot_sync(0xffffffffu, small);
    const int m = __popc(bm);
    if (small) {
        const int rank = __popc(bm & ((1u << lane) - 1u));
        sc[wid][rank] = a;
        st[wid][rank] = 1 << (13 - lane);
    }
    __syncwarp();

    // survivor scatter: lane = subset mask (one pass for ~95% of samples)
    const float invS = __expf(-logS);
    const int nm = 1 << m;
    for (int mask = lane; mask < nm; mask += 32) {
        float c = 0.0f;
        int tog = 0;
        for (int j = 0; j < m; j++)
            if ((mask >> j) & 1) { c += sc[wid][j]; tog ^= st[wid][j]; }
        if (c < 30.0f)
            atomicAdd(&g_avg[idx ^ tog], __expf(-c) * invS);
    }

    // block entropy partial -> one atomic per block
    __syncthreads();
    if (tid < WPB) {
        float t = wents[tid];
#pragma unroll
        for (int off = WPB / 2; off > 0; off >>= 1)
            t += __shfl_xor_sync((1u << WPB) - 1u, t, off);
        if (tid == 0) atomicAdd(&g_ent_sum, t);
    }

    // ---- grid barrier (all blocks resident by construction) ----
    __threadfence();                 // release: scatter visible before arrival
    __syncthreads();
    if (tid == 0) {
        atomicAdd((int*)&g_done, 1);
        while (g_done < NBLK) __nanosleep(64);   // plain L2 load, no RMW storm
    }
    __syncthreads();
    __threadfence();                 // acquire: see other blocks' g_avg writes

    // ---- phase 2: histogram fold (32 entries per block) ----
    float ms = 0.0f;
    if (tid < HPB) {
        const int i = blockIdx.x * HPB + tid;
        const float av = g_avg[i] * (1.0f / (float)NSAMP);
        g_avg[i] = 0.0f;             // restore zeros for next replay
        ms = av * __logf(av + 1e-9f);
    }
    if (tid < 32) {
        ms = warp_sum(ms);
        if (tid == 0) {
            atomicAdd(&g_hist_sum, ms);
            __threadfence();
            const int d = atomicAdd(&g_done2, 1);
            if (d == NBLK - 1) {
                // every block has exited the spin (it reached here), so
                // resetting g_done is safe now.
                const float hs = atomicAdd(&g_hist_sum, 0.0f);
                const float es = atomicAdd(&g_ent_sum, 0.0f);
                // el = entro_mean - mean_entro = es/N + sum a*log(a+eps)
                out[Q_ELEMS] = es * (1.0f / (float)NSAMP) + hs;
                g_hist_sum = 0.0f;
                g_ent_sum  = 0.0f;
                g_done     = 0;
                g_done2    = 0;
            }
        }
    }
}

extern "C" void kernel_launch(void* const* d_in, const int* in_sizes, int n_in,
                              void* d_out, int out_size) {
    const float* x = (const float*)d_in[0];
    float* out = (float*)d_out;
    lfq_fused<<<NBLK, 32 * WPB>>>(x, out);
}